// round 7
// baseline (speedup 1.0000x reference)
#include <cuda_runtime.h>

#define F_TOTAL 256
#define H 16
#define BATCH 32768
#define GF 16                    // features per CTA
#define NGROUPS (F_TOTAL / GF)   // 16
#define TPB 128
#define RB 4                     // batch rows per thread

typedef unsigned long long u64;

// ---- f32x2 packed helpers (sm_103a) ----
__device__ __forceinline__ u64 pack2(float lo, float hi) {
    u64 r;
    asm("mov.b64 %0, {%1, %2};" : "=l"(r)
        : "r"(__float_as_uint(lo)), "r"(__float_as_uint(hi)));
    return r;
}
__device__ __forceinline__ u64 bcast2(float v) {
    u64 r;
    unsigned u = __float_as_uint(v);
    asm("mov.b64 %0, {%1, %1};" : "=l"(r) : "r"(u));
    return r;
}
__device__ __forceinline__ void ffma2(u64& d, u64 a, u64 b) {
    asm("fma.rn.f32x2 %0, %1, %2, %0;" : "+l"(d) : "l"(a), "l"(b));
}
__device__ __forceinline__ u64 fma2v(u64 a, u64 b, u64 c) {
    u64 d;
    asm("fma.rn.f32x2 %0, %1, %2, %3;" : "=l"(d) : "l"(a), "l"(b), "l"(c));
    return d;
}
__device__ __forceinline__ float lo32(u64 v) {
    return __uint_as_float((unsigned)v);
}
__device__ __forceinline__ float hi32(u64 v) {
    return __uint_as_float((unsigned)(v >> 32));
}
__device__ __forceinline__ u64 relu2(u64 v) {
    return pack2(fmaxf(lo32(v), 0.f), fmaxf(hi32(v), 0.f));
}

__global__ void igann_init_kernel(float* __restrict__ out,
                                  const float* __restrict__ bias_b) {
    int i = blockIdx.x * blockDim.x + threadIdx.x;
    if (i < BATCH) out[i] = bias_b[0];
}

// One feature's full subnet for RB batch rows.
// xdup[r] = {x,x}; W2 j-pair packed (not duplicated); W1/b1 duplicated.
__device__ __forceinline__ void feature_body(
    int fi, const u64* __restrict__ xdup,
    const ulonglong2* __restrict__ sW1dup,   // [GF*H]   {dup w1, dup b1}
    const ulonglong2* __restrict__ sW2p,     // [GF*H*4] j-pair packed
    const ulonglong2* __restrict__ sB2p,     // [GF*4]   raw-aliased pairs
    const ulonglong2* __restrict__ sW3p,     // [GF*4]   raw-aliased pairs
    const u64* __restrict__ sA0,             // [GF]     {a, 0}
    u64* __restrict__ oA)                    // [RB] packed sums
{
    const ulonglong2* w1p = sW1dup + fi * H;
    const ulonglong2* w2p = sW2p + fi * (H * 4);
    const ulonglong2* b2p = sB2p + fi * 4;

    u64 acc[RB][8];

    // i = 0 peel: accumulators initialized via 3-operand fma2 with b2
    {
        ulonglong2 wb = w1p[0];
        u64 hd[RB];
        #pragma unroll
        for (int r = 0; r < RB; r++)
            hd[r] = relu2(fma2v(xdup[r], wb.x, wb.y));
        #pragma unroll
        for (int q = 0; q < 4; q++) {
            ulonglong2 w  = w2p[q];
            ulonglong2 bv = b2p[q];
            #pragma unroll
            for (int r = 0; r < RB; r++) {
                acc[r][2 * q]     = fma2v(w.x, hd[r], bv.x);
                acc[r][2 * q + 1] = fma2v(w.y, hd[r], bv.y);
            }
        }
    }
    #pragma unroll
    for (int i = 1; i < H; i++) {
        ulonglong2 wb = w1p[i];
        u64 hd[RB];
        #pragma unroll
        for (int r = 0; r < RB; r++)
            hd[r] = relu2(fma2v(xdup[r], wb.x, wb.y));
        #pragma unroll
        for (int q = 0; q < 4; q++) {
            ulonglong2 w = w2p[i * 4 + q];
            #pragma unroll
            for (int r = 0; r < RB; r++) {
                ffma2(acc[r][2 * q],     w.x, hd[r]);
                ffma2(acc[r][2 * q + 1], w.y, hd[r]);
            }
        }
    }
    // fc3: relu(h2) . W3, j-pair packed
    #pragma unroll
    for (int q = 0; q < 4; q++) {
        ulonglong2 w3 = sW3p[fi * 4 + q];
        #pragma unroll
        for (int r = 0; r < RB; r++) {
            ffma2(oA[r], relu2(acc[r][2 * q]),     w3.x);
            ffma2(oA[r], relu2(acc[r][2 * q + 1]), w3.y);
        }
    }
    // linear term: {a,0} packed adds a*x to the lo lane only
    u64 a0 = sA0[fi];
    #pragma unroll
    for (int r = 0; r < RB; r++)
        ffma2(oA[r], a0, xdup[r]);
}

__global__ __launch_bounds__(TPB, 3) void igann_kernel(
    const float* __restrict__ x,   // [B, F]
    const float* __restrict__ la,  // [F]
    const float* __restrict__ W1,  // [F, H]
    const float* __restrict__ b1,  // [F, H]
    const float* __restrict__ W2,  // [F, H(out), H(in)]
    const float* __restrict__ b2,  // [F, H]
    const float* __restrict__ W3,  // [F, H]
    const float* __restrict__ b3,  // [F]
    float* __restrict__ out)       // [B]
{
    __shared__ ulonglong2 sW1dup[GF * H];   // 4 KB  {dup w1, dup b1}
    __shared__ ulonglong2 sW2p[GF * H * 4]; // 16 KB j-pair packed W2^T
    __shared__ ulonglong2 sB2p[GF * 4];     // raw b2 rows pair-aliased
    __shared__ ulonglong2 sW3p[GF * 4];     // raw W3 rows pair-aliased
    __shared__ u64 sA0[GF];                 // {a, 0}
    __shared__ float sB3sum;

    const int g   = blockIdx.y;
    const int tid = threadIdx.x;
    const int f0  = g * GF;

    // ---- stage weights ----
    #pragma unroll
    for (int k = 0; k < 8; k++) {
        int e  = tid + k * TPB;       // 0..1023
        int fi = e >> 6;
        int i  = (e >> 2) & 15;
        int q  = e & 3;
        const float* wp = W2 + (size_t)(f0 + fi) * (H * H) + i;
        ulonglong2 v;
        v.x = pack2(wp[(4 * q + 0) * H], wp[(4 * q + 1) * H]);
        v.y = pack2(wp[(4 * q + 2) * H], wp[(4 * q + 3) * H]);
        sW2p[e] = v;
    }
    #pragma unroll
    for (int k = 0; k < 2; k++) {
        int e = tid + k * TPB;        // 0..255 == GF*H
        ulonglong2 v;
        v.x = bcast2(W1[f0 * H + e]);
        v.y = bcast2(b1[f0 * H + e]);
        sW1dup[e] = v;
        ((float*)sB2p)[e] = b2[f0 * H + e];
        ((float*)sW3p)[e] = W3[f0 * H + e];
    }
    if (tid < GF) sA0[tid] = pack2(la[f0 + tid], 0.f);
    if (tid == 0) {
        float s = 0.f;
        #pragma unroll
        for (int f = 0; f < GF; f++) s += b3[f0 + f];
        sB3sum = s;
    }
    __syncthreads();

    // ---- compute: RB rows per thread ----
    const int b0 = blockIdx.x * (TPB * RB) + tid;
    const float* xbase = x + (size_t)b0 * F_TOTAL + f0;

    u64 oA[RB];
    #pragma unroll
    for (int r = 0; r < RB; r++) oA[r] = 0ull;

    #pragma unroll 1       // body = 2 features
    for (int o2 = 0; o2 < 8; o2++) {
        float2 xq[RB];
        #pragma unroll
        for (int r = 0; r < RB; r++)
            xq[r] = *(const float2*)(xbase + (size_t)r * TPB * F_TOTAL + o2 * 2);

        {
            u64 xdup[RB];
            #pragma unroll
            for (int r = 0; r < RB; r++) xdup[r] = bcast2(xq[r].x);
            feature_body(o2 * 2, xdup, sW1dup, sW2p, sB2p, sW3p, sA0, oA);
        }
        {
            u64 xdup[RB];
            #pragma unroll
            for (int r = 0; r < RB; r++) xdup[r] = bcast2(xq[r].y);
            feature_body(o2 * 2 + 1, xdup, sW1dup, sW2p, sB2p, sW3p, sA0, oA);
        }
    }

    const float base = sB3sum;
    #pragma unroll
    for (int r = 0; r < RB; r++)
        atomicAdd(&out[b0 + r * TPB], lo32(oA[r]) + hi32(oA[r]) + base);
}

extern "C" void kernel_launch(void* const* d_in, const int* in_sizes, int n_in,
                              void* d_out, int out_size) {
    const float* x      = (const float*)d_in[0];
    const float* la     = (const float*)d_in[1];
    const float* bias_b = (const float*)d_in[2];
    const float* W1     = (const float*)d_in[3];
    const float* b1     = (const float*)d_in[4];
    const float* W2     = (const float*)d_in[5];
    const float* b2     = (const float*)d_in[6];
    const float* W3     = (const float*)d_in[7];
    const float* b3     = (const float*)d_in[8];
    float* out = (float*)d_out;

    igann_init_kernel<<<BATCH / 256, 256>>>(out, bias_b);

    dim3 grid(BATCH / (TPB * RB), NGROUPS);
    igann_kernel<<<grid, TPB>>>(x, la, W1, b1, W2, b2, W3, b3, out);
}

// round 9
// speedup vs baseline: 1.4124x; 1.4124x over previous
#include <cuda_runtime.h>
#include <cuda_bf16.h>
#include <cstdint>

typedef unsigned int u32;
typedef unsigned long long u64;

#define F_TOTAL 256
#define H 16
#define BATCH 32768
#define GF 16                    // features per CTA
#define NGROUPS (F_TOTAL / GF)   // 16
#define TPB 128                  // 4 warps; warp w owns rows w*32..w*32+31

// ---- packed f32x2 helpers ----
__device__ __forceinline__ u64 pack2(float lo, float hi) {
    u64 r;
    asm("mov.b64 %0, {%1, %2};" : "=l"(r)
        : "r"(__float_as_uint(lo)), "r"(__float_as_uint(hi)));
    return r;
}
__device__ __forceinline__ void ffma2(u64& d, u64 a, u64 b) {
    asm("fma.rn.f32x2 %0, %1, %2, %0;" : "+l"(d) : "l"(a), "l"(b));
}
__device__ __forceinline__ u64 add2(u64 a, u64 b) {
    u64 d; asm("add.rn.f32x2 %0, %1, %2;" : "=l"(d) : "l"(a), "l"(b)); return d;
}
__device__ __forceinline__ float lo32(u64 v) { return __uint_as_float((u32)v); }
__device__ __forceinline__ float hi32(u64 v) { return __uint_as_float((u32)(v >> 32)); }
__device__ __forceinline__ u64 relu2(u64 v) {
    return pack2(fmaxf(lo32(v), 0.f), fmaxf(hi32(v), 0.f));
}
// {trunc_bf16(a) -> low half, trunc_bf16(b) -> high half}
__device__ __forceinline__ u32 prmt_hi16(u32 a, u32 b) {
    u32 d;
    asm("prmt.b32 %0, %1, %2, 0x7632;" : "=r"(d) : "r"(a), "r"(b));
    return d;
}
// bf16x2: first arg -> LOW half, second -> HIGH half
__device__ __forceinline__ u32 cvt_bf16x2(float lo_v, float hi_v) {
    u32 d;
    asm("cvt.rn.bf16x2.f32 %0, %1, %2;" : "=r"(d) : "f"(hi_v), "f"(lo_v));
    return d;
}
__device__ __forceinline__ float hif(float h) {   // truncated-bf16 value as f32
    return __uint_as_float(__float_as_uint(h) & 0xffff0000u);
}

// ---- mma.sync m16n8k16 bf16 (base PTX, sm_80+) ----
__device__ __forceinline__ void mma_z(float* d, const u32* a, uint2 b) {
    asm volatile("mma.sync.aligned.m16n8k16.row.col.f32.bf16.bf16.f32 "
        "{%0,%1,%2,%3}, {%4,%5,%6,%7}, {%8,%9}, {%10,%10,%10,%10};"
        : "=f"(d[0]), "=f"(d[1]), "=f"(d[2]), "=f"(d[3])
        : "r"(a[0]), "r"(a[1]), "r"(a[2]), "r"(a[3]),
          "r"(b.x), "r"(b.y), "f"(0.f));
}
__device__ __forceinline__ void mma_acc(float* d, const u32* a, uint2 b) {
    asm volatile("mma.sync.aligned.m16n8k16.row.col.f32.bf16.bf16.f32 "
        "{%0,%1,%2,%3}, {%4,%5,%6,%7}, {%8,%9}, {%0,%1,%2,%3};"
        : "+f"(d[0]), "+f"(d[1]), "+f"(d[2]), "+f"(d[3])
        : "r"(a[0]), "r"(a[1]), "r"(a[2]), "r"(a[3]),
          "r"(b.x), "r"(b.y));
}

__global__ void igann_init_kernel(float* __restrict__ out,
                                  const float* __restrict__ bias_b) {
    int i = blockIdx.x * blockDim.x + threadIdx.x;
    if (i < BATCH) out[i] = bias_b[0];
}

__global__ __launch_bounds__(TPB, 4) void igann_mma_kernel(
    const float* __restrict__ x,   // [B, F]
    const float* __restrict__ la,  // [F]
    const float* __restrict__ W1,  // [F, H]
    const float* __restrict__ b1,  // [F, H]
    const float* __restrict__ W2,  // [F, H(out j), H(in i)]
    const float* __restrict__ b2,  // [F, H]
    const float* __restrict__ W3,  // [F, H]
    const float* __restrict__ b3,  // [F]
    float* __restrict__ out)       // [B]
{
    // B fragments, prepacked per lane: [fi][kt(hi/lo)][ns][lane] -> uint2{b0,b1}
    __shared__ uint2 sBfrag[GF * 128];     // 16 KB
    __shared__ float4 sW1B1[GF * 8];       // (w1_i,b1_i,w1_{i+1},b1_{i+1})
    __shared__ u64 sB2p[GF * 8];           // b2 j-pairs
    __shared__ u64 sW3p[GF * 8];           // W3 j-pairs
    __shared__ float sA[GF];
    __shared__ float sB3sum;

    const int tid  = threadIdx.x;
    const int lane = tid & 31;
    const int wid  = tid >> 5;
    const int f0   = blockIdx.y * GF;
    const int row  = blockIdx.x * TPB + tid;

    // ---- stage B fragments: W2 split hi(trunc) / lo(residual bf16) ----
    // frag layout (m16n8k16, col-major B): b0: k=(lane%4)*2 +{0,1}, n=ns*8+lane/4
    //                                      b1: k=(lane%4)*2+8+{0,1}
    #pragma unroll
    for (int t = 0; t < 16; t++) {
        int e    = tid + t * TPB;          // 0..2047
        int fi   = e >> 7;
        int kt   = (e >> 6) & 1;           // 0 = Whi, 1 = Wlo
        int ns   = (e >> 5) & 1;
        int ln   = e & 31;
        int n    = ns * 8 + (ln >> 2);     // output j
        int kb   = (ln & 3) * 2;
        const float* wrow = W2 + (size_t)(f0 + fi) * 256 + n * H;
        u32 pk[2];
        #pragma unroll
        for (int hh = 0; hh < 2; hh++) {
            float w0 = wrow[kb + 8 * hh];
            float w1 = wrow[kb + 8 * hh + 1];
            u32 s0, s1;
            if (kt == 0) {
                s0 = __float_as_uint(w0) >> 16;
                s1 = __float_as_uint(w1) >> 16;
            } else {
                s0 = (u32)__bfloat16_as_ushort(__float2bfloat16(w0 - hif(w0)));
                s1 = (u32)__bfloat16_as_ushort(__float2bfloat16(w1 - hif(w1)));
            }
            pk[hh] = s0 | (s1 << 16);
        }
        sBfrag[e] = make_uint2(pk[0], pk[1]);
    }
    // ---- stage W1/b1, b2/W3 pairs ----
    {
        int fi = tid >> 3, p = tid & 7, i = 2 * p;   // exactly GF*8 == TPB
        float4 v;
        v.x = W1[(f0 + fi) * H + i];     v.y = b1[(f0 + fi) * H + i];
        v.z = W1[(f0 + fi) * H + i + 1]; v.w = b1[(f0 + fi) * H + i + 1];
        sW1B1[fi * 8 + p] = v;
        sB2p[fi * 8 + p] = pack2(b2[(f0 + fi) * H + i], b2[(f0 + fi) * H + i + 1]);
        sW3p[fi * 8 + p] = pack2(W3[(f0 + fi) * H + i], W3[(f0 + fi) * H + i + 1]);
    }
    if (tid < GF) sA[tid] = la[f0 + tid];
    if (tid == 0) {
        float s = 0.f;
        #pragma unroll
        for (int f = 0; f < GF; f++) s += b3[f0 + f];
        sB3sum = s;
    }
    __syncthreads();

    float lin = 0.f;
    u64 acc[4] = {0ull, 0ull, 0ull, 0ull};   // packed j-pair sums per row-group

    #pragma unroll 1
    for (int c = 0; c < 4; c++) {
        float4 xq = *(const float4*)(x + (size_t)row * F_TOTAL + f0 + c * 4);
        float xcs[4] = {xq.x, xq.y, xq.z, xq.w};

        #pragma unroll
        for (int fc = 0; fc < 4; fc++) {
            const int fi = c * 4 + fc;
            const float xc = xcs[fc];
            lin = fmaf(sA[fi], xc, lin);            // own row's linear term

            const float4 wbA = sW1B1[fi * 8 + (lane & 3)];      // i-pair (lane%4)*2
            const float4 wbB = sW1B1[fi * 8 + (lane & 3) + 4];  // i-pair +8

            // A fragments: h1 computed directly into fragment slots.
            u32 ahi[2][4], alo[2][4];               // [mtile][reg]
            #pragma unroll
            for (int rg = 0; rg < 4; rg++) {        // row = lane/4 + 8*rg (warp-rel)
                float xv = __shfl_sync(0xffffffffu, xc, (lane >> 2) + 8 * rg);
                float h0 = fmaxf(fmaf(xv, wbA.x, wbA.y), 0.f);
                float h1 = fmaxf(fmaf(xv, wbA.z, wbA.w), 0.f);
                float h2 = fmaxf(fmaf(xv, wbB.x, wbB.y), 0.f);
                float h3 = fmaxf(fmaf(xv, wbB.z, wbB.w), 0.f);
                int mt = rg >> 1, sl = rg & 1;      // a0/a1: i-pair0; a2/a3: i-pair1
                ahi[mt][sl]     = prmt_hi16(__float_as_uint(h0), __float_as_uint(h1));
                ahi[mt][2 + sl] = prmt_hi16(__float_as_uint(h2), __float_as_uint(h3));
                alo[mt][sl]     = cvt_bf16x2(h0 - hif(h0), h1 - hif(h1));
                alo[mt][2 + sl] = cvt_bf16x2(h2 - hif(h2), h3 - hif(h3));
            }

            const uint2 bh0 = sBfrag[fi * 128 + lane];        // Whi, ns=0
            const uint2 bh1 = sBfrag[fi * 128 + 32 + lane];   // Whi, ns=1
            const uint2 bl0 = sBfrag[fi * 128 + 64 + lane];   // Wlo, ns=0
            const uint2 bl1 = sBfrag[fi * 128 + 96 + lane];   // Wlo, ns=1

            // D = hi*Whi + lo*Whi + hi*Wlo   (drops only lo*Wlo ~ 2^-16)
            float d[2][2][4];
            #pragma unroll
            for (int mt = 0; mt < 2; mt++) {
                mma_z  (d[mt][0], ahi[mt], bh0);
                mma_acc(d[mt][0], alo[mt], bh0);
                mma_acc(d[mt][0], ahi[mt], bl0);
                mma_z  (d[mt][1], ahi[mt], bh1);
                mma_acc(d[mt][1], alo[mt], bh1);
                mma_acc(d[mt][1], ahi[mt], bl1);
            }

            // epilogue: h2 = relu(D + b2); acc += h2 .* W3 (packed j-pairs)
            const u64 b2a = sB2p[fi * 8 + (lane & 3)];
            const u64 b2b = sB2p[fi * 8 + (lane & 3) + 4];
            const u64 w3a = sW3p[fi * 8 + (lane & 3)];
            const u64 w3b = sW3p[fi * 8 + (lane & 3) + 4];
            #pragma unroll
            for (int mt = 0; mt < 2; mt++) {
                #pragma unroll
                for (int hh = 0; hh < 2; hh++) {     // d idx {0,1} row g; {2,3} row g+8
                    int rg = 2 * mt + hh;
                    u64 p0 = pack2(d[mt][0][2 * hh], d[mt][0][2 * hh + 1]);
                    u64 p1 = pack2(d[mt][1][2 * hh], d[mt][1][2 * hh + 1]);
                    ffma2(acc[rg], relu2(add2(p0, b2a)), w3a);
                    ffma2(acc[rg], relu2(add2(p1, b2b)), w3b);
                }
            }
        }
    }

    // ---- reduce: quad butterfly per row-group; fold lin via shfl; one atomic/row ----
    const float base = sB3sum;
    #pragma unroll
    for (int rg = 0; rg < 4; rg++) {
        float s = lo32(acc[rg]) + hi32(acc[rg]);
        s += __shfl_xor_sync(0xffffffffu, s, 1);
        s += __shfl_xor_sync(0xffffffffu, s, 2);
        float linr = __shfl_sync(0xffffffffu, lin, (lane >> 2) + 8 * rg);
        if ((lane & 3) == 0) {
            int r = blockIdx.x * TPB + wid * 32 + (lane >> 2) + 8 * rg;
            atomicAdd(&out[r], s + linr + base);
        }
    }
}

extern "C" void kernel_launch(void* const* d_in, const int* in_sizes, int n_in,
                              void* d_out, int out_size) {
    const float* x      = (const float*)d_in[0];
    const float* la     = (const float*)d_in[1];
    const float* bias_b = (const float*)d_in[2];
    const float* W1     = (const float*)d_in[3];
    const float* b1     = (const float*)d_in[4];
    const float* W2     = (const float*)d_in[5];
    const float* b2     = (const float*)d_in[6];
    const float* W3     = (const float*)d_in[7];
    const float* b3     = (const float*)d_in[8];
    float* out = (float*)d_out;

    igann_init_kernel<<<BATCH / 256, 256>>>(out, bias_b);

    dim3 grid(BATCH / TPB, NGROUPS);
    igann_mma_kernel<<<grid, TPB>>>(x, la, W1, b1, W2, b2, W3, b3, out);
}

// round 10
// speedup vs baseline: 1.4574x; 1.0319x over previous
#include <cuda_runtime.h>
#include <cuda_bf16.h>
#include <cstdint>

typedef unsigned int u32;
typedef unsigned long long u64;

#define F_TOTAL 256
#define H 16
#define BATCH 32768
#define GF 16                    // features per CTA
#define NGROUPS (F_TOTAL / GF)   // 16
#define TPB 128                  // 4 warps; warp w owns rows w*32..w*32+31

// ---- helpers ----
__device__ __forceinline__ u64 pack2(float lo, float hi) {
    u64 r;
    asm("mov.b64 %0, {%1, %2};" : "=l"(r)
        : "r"(__float_as_uint(lo)), "r"(__float_as_uint(hi)));
    return r;
}
__device__ __forceinline__ float lo32(u64 v) { return __uint_as_float((u32)v); }
__device__ __forceinline__ float hi32(u64 v) { return __uint_as_float((u32)(v >> 32)); }
// {trunc_bf16(a) -> low half, trunc_bf16(b) -> high half}
__device__ __forceinline__ u32 prmt_hi16(u32 a, u32 b) {
    u32 d;
    asm("prmt.b32 %0, %1, %2, 0x7632;" : "=r"(d) : "r"(a), "r"(b));
    return d;
}
// bf16x2: first arg -> LOW half, second -> HIGH half
__device__ __forceinline__ u32 cvt_bf16x2(float lo_v, float hi_v) {
    u32 d;
    asm("cvt.rn.bf16x2.f32 %0, %1, %2;" : "=r"(d) : "f"(hi_v), "f"(lo_v));
    return d;
}
__device__ __forceinline__ float hif(float h) {   // truncated-bf16 value as f32
    return __uint_as_float(__float_as_uint(h) & 0xffff0000u);
}

// ---- mma.sync m16n8k16 bf16 (base PTX, sm_80+) ----
// init accumulator with {c0, c1, c0, c1} (per-column bias)
__device__ __forceinline__ void mma_bias(float* d, const u32* a, uint2 b,
                                         float c0, float c1) {
    asm volatile("mma.sync.aligned.m16n8k16.row.col.f32.bf16.bf16.f32 "
        "{%0,%1,%2,%3}, {%4,%5,%6,%7}, {%8,%9}, {%10,%11,%10,%11};"
        : "=f"(d[0]), "=f"(d[1]), "=f"(d[2]), "=f"(d[3])
        : "r"(a[0]), "r"(a[1]), "r"(a[2]), "r"(a[3]),
          "r"(b.x), "r"(b.y), "f"(c0), "f"(c1));
}
__device__ __forceinline__ void mma_acc(float* d, const u32* a, uint2 b) {
    asm volatile("mma.sync.aligned.m16n8k16.row.col.f32.bf16.bf16.f32 "
        "{%0,%1,%2,%3}, {%4,%5,%6,%7}, {%8,%9}, {%0,%1,%2,%3};"
        : "+f"(d[0]), "+f"(d[1]), "+f"(d[2]), "+f"(d[3])
        : "r"(a[0]), "r"(a[1]), "r"(a[2]), "r"(a[3]),
          "r"(b.x), "r"(b.y));
}

__global__ void igann_init_kernel(float* __restrict__ out,
                                  const float* __restrict__ bias_b) {
    int i = blockIdx.x * blockDim.x + threadIdx.x;
    if (i < BATCH) out[i] = bias_b[0];
}

__global__ __launch_bounds__(TPB, 4) void igann_mma_kernel(
    const float* __restrict__ x,   // [B, F]
    const float* __restrict__ la,  // [F]
    const float* __restrict__ W1,  // [F, H]
    const float* __restrict__ b1,  // [F, H]
    const float* __restrict__ W2,  // [F, H(out j), H(in i)]
    const float* __restrict__ b2,  // [F, H]
    const float* __restrict__ W3,  // [F, H]
    const float* __restrict__ b3,  // [F]
    float* __restrict__ out)       // [B]
{
    // B fragments, prepacked per lane: [fi][kt(hi/lo)][ns][lane] -> uint2{b0,b1}
    __shared__ uint2 sBfrag[GF * 128];     // 16 KB
    __shared__ float4 sW1B1[GF * 8];       // (w1_i,b1_i,w1_{i+1},b1_{i+1})
    __shared__ u64 sB2p[GF * 8];           // b2 j-pairs
    __shared__ u64 sW3p[GF * 8];           // W3 j-pairs
    __shared__ float sA[GF];
    __shared__ float sB3sum;

    const int tid  = threadIdx.x;
    const int lane = tid & 31;
    const int wid  = tid >> 5;
    const int f0   = blockIdx.y * GF;

    // ---- stage B fragments: W2 split hi(trunc) / lo(residual bf16) ----
    #pragma unroll
    for (int t = 0; t < 16; t++) {
        int e    = tid + t * TPB;          // 0..2047
        int fi   = e >> 7;
        int kt   = (e >> 6) & 1;           // 0 = Whi, 1 = Wlo
        int ns   = (e >> 5) & 1;
        int ln   = e & 31;
        int n    = ns * 8 + (ln >> 2);
        int kb   = (ln & 3) * 2;
        const float* wrow = W2 + (size_t)(f0 + fi) * 256 + n * H;
        u32 pk[2];
        #pragma unroll
        for (int hh = 0; hh < 2; hh++) {
            float w0 = wrow[kb + 8 * hh];
            float w1 = wrow[kb + 8 * hh + 1];
            u32 s0, s1;
            if (kt == 0) {
                s0 = __float_as_uint(w0) >> 16;
                s1 = __float_as_uint(w1) >> 16;
            } else {
                s0 = (u32)__bfloat16_as_ushort(__float2bfloat16(w0 - hif(w0)));
                s1 = (u32)__bfloat16_as_ushort(__float2bfloat16(w1 - hif(w1)));
            }
            pk[hh] = s0 | (s1 << 16);
        }
        sBfrag[e] = make_uint2(pk[0], pk[1]);
    }
    // ---- stage W1/b1, b2/W3 pairs ----
    {
        int fi = tid >> 3, p = tid & 7, i = 2 * p;   // GF*8 == TPB
        float4 v;
        v.x = W1[(f0 + fi) * H + i];     v.y = b1[(f0 + fi) * H + i];
        v.z = W1[(f0 + fi) * H + i + 1]; v.w = b1[(f0 + fi) * H + i + 1];
        sW1B1[fi * 8 + p] = v;
        sB2p[fi * 8 + p] = pack2(b2[(f0 + fi) * H + i], b2[(f0 + fi) * H + i + 1]);
        sW3p[fi * 8 + p] = pack2(W3[(f0 + fi) * H + i], W3[(f0 + fi) * H + i + 1]);
    }
    if (tid < GF) sA[tid] = la[f0 + tid];
    if (tid == 0) {
        float s = 0.f;
        #pragma unroll
        for (int f = 0; f < GF; f++) s += b3[f0 + f];
        sB3sum = s;
    }
    __syncthreads();

    // fragment-row base: this thread serves rows rowbase + 8*rg (rg = 0..3)
    const int rowbase = blockIdx.x * TPB + wid * 32 + (lane >> 2);
    const bool reducer = (lane & 3) == 0;

    float lin[4] = {0.f, 0.f, 0.f, 0.f};
    float acc[4] = {0.f, 0.f, 0.f, 0.f};

    #pragma unroll 1
    for (int c = 0; c < 4; c++) {
        // x chunks for the 4 fragment rows; quad-lanes hit the same address
        float4 xr[4];
        #pragma unroll
        for (int rg = 0; rg < 4; rg++)
            xr[rg] = *(const float4*)(x + (size_t)(rowbase + 8 * rg) * F_TOTAL
                                        + f0 + c * 4);

        #pragma unroll
        for (int fc = 0; fc < 4; fc++) {
            const int fi = c * 4 + fc;
            float xf[4];
            #pragma unroll
            for (int rg = 0; rg < 4; rg++)
                xf[rg] = (fc == 0) ? xr[rg].x : (fc == 1) ? xr[rg].y
                       : (fc == 2) ? xr[rg].z : xr[rg].w;

            // linear term: only the reducer lane of each quad accumulates
            if (reducer) {
                const float aF = sA[fi];
                #pragma unroll
                for (int rg = 0; rg < 4; rg++)
                    lin[rg] = fmaf(aF, xf[rg], lin[rg]);
            }

            const float4 wbA = sW1B1[fi * 8 + (lane & 3)];      // i-pair (lane%4)*2
            const float4 wbB = sW1B1[fi * 8 + (lane & 3) + 4];  // i-pair +8

            // A fragments: h1 computed directly into fragment slots (no shfl)
            u32 ahi[2][4], alo[2][4];
            #pragma unroll
            for (int rg = 0; rg < 4; rg++) {
                float xv = xf[rg];
                float h0 = fmaxf(fmaf(xv, wbA.x, wbA.y), 0.f);
                float h1 = fmaxf(fmaf(xv, wbA.z, wbA.w), 0.f);
                float h2 = fmaxf(fmaf(xv, wbB.x, wbB.y), 0.f);
                float h3 = fmaxf(fmaf(xv, wbB.z, wbB.w), 0.f);
                int mt = rg >> 1, sl = rg & 1;
                ahi[mt][sl]     = prmt_hi16(__float_as_uint(h0), __float_as_uint(h1));
                ahi[mt][2 + sl] = prmt_hi16(__float_as_uint(h2), __float_as_uint(h3));
                alo[mt][sl]     = cvt_bf16x2(h0 - hif(h0), h1 - hif(h1));
                alo[mt][2 + sl] = cvt_bf16x2(h2 - hif(h2), h3 - hif(h3));
            }

            const uint2 bh0 = sBfrag[fi * 128 + lane];
            const uint2 bh1 = sBfrag[fi * 128 + 32 + lane];
            const uint2 bl0 = sBfrag[fi * 128 + 64 + lane];
            const uint2 bl1 = sBfrag[fi * 128 + 96 + lane];

            const u64 b2a = sB2p[fi * 8 + (lane & 3)];
            const u64 b2b = sB2p[fi * 8 + (lane & 3) + 4];

            // D = b2 + hi*Whi + lo*Whi + hi*Wlo
            float d[2][2][4];
            #pragma unroll
            for (int mt = 0; mt < 2; mt++) {
                mma_bias(d[mt][0], ahi[mt], bh0, lo32(b2a), hi32(b2a));
                mma_acc (d[mt][0], alo[mt], bh0);
                mma_acc (d[mt][0], ahi[mt], bl0);
                mma_bias(d[mt][1], ahi[mt], bh1, lo32(b2b), hi32(b2b));
                mma_acc (d[mt][1], alo[mt], bh1);
                mma_acc (d[mt][1], ahi[mt], bl1);
            }

            // scalar epilogue: acc[rg] += relu(D) . W3  (no packing)
            const u64 w3a = sW3p[fi * 8 + (lane & 3)];
            const u64 w3b = sW3p[fi * 8 + (lane & 3) + 4];
            const float w30 = lo32(w3a), w31 = hi32(w3a);
            const float w38 = lo32(w3b), w39 = hi32(w3b);
            #pragma unroll
            for (int mt = 0; mt < 2; mt++) {
                #pragma unroll
                for (int hh = 0; hh < 2; hh++) {
                    int rg = 2 * mt + hh;
                    float t = acc[rg];
                    t = fmaf(fmaxf(d[mt][0][2 * hh],     0.f), w30, t);
                    t = fmaf(fmaxf(d[mt][0][2 * hh + 1], 0.f), w31, t);
                    t = fmaf(fmaxf(d[mt][1][2 * hh],     0.f), w38, t);
                    t = fmaf(fmaxf(d[mt][1][2 * hh + 1], 0.f), w39, t);
                    acc[rg] = t;
                }
            }
        }
    }

    // ---- reduce: quad butterfly per row-group; one atomic per row ----
    const float base = sB3sum;
    #pragma unroll
    for (int rg = 0; rg < 4; rg++) {
        float s = acc[rg];
        s += __shfl_xor_sync(0xffffffffu, s, 1);
        s += __shfl_xor_sync(0xffffffffu, s, 2);
        if (reducer)
            atomicAdd(&out[rowbase + 8 * rg], s + lin[rg] + base);
    }
}

extern "C" void kernel_launch(void* const* d_in, const int* in_sizes, int n_in,
                              void* d_out, int out_size) {
    const float* x      = (const float*)d_in[0];
    const float* la     = (const float*)d_in[1];
    const float* bias_b = (const float*)d_in[2];
    const float* W1     = (const float*)d_in[3];
    const float* b1     = (const float*)d_in[4];
    const float* W2     = (const float*)d_in[5];
    const float* b2     = (const float*)d_in[6];
    const float* W3     = (const float*)d_in[7];
    const float* b3     = (const float*)d_in[8];
    float* out = (float*)d_out;

    igann_init_kernel<<<BATCH / 256, 256>>>(out, bias_b);

    dim3 grid(BATCH / TPB, NGROUPS);
    igann_mma_kernel<<<grid, TPB>>>(x, la, W1, b1, W2, b2, W3, b3, out);
}

// round 11
// speedup vs baseline: 1.5740x; 1.0799x over previous
#include <cuda_runtime.h>
#include <cuda_bf16.h>
#include <cstdint>

typedef unsigned int u32;
typedef unsigned long long u64;

#define F_TOTAL 256
#define H 16
#define BATCH 32768
#define GF 16                    // features per CTA
#define NGROUPS (F_TOTAL / GF)   // 16
#define TPB 128                  // 4 warps
#define MT 2                     // 32-row blocks per warp
#define ROWS_CTA (TPB * MT)      // 256
#define XSTRIDE 20               // floats; conflict-free for 8-row strided LDS

// ---- helpers ----
__device__ __forceinline__ u64 pack2(float lo, float hi) {
    u64 r;
    asm("mov.b64 %0, {%1, %2};" : "=l"(r)
        : "r"(__float_as_uint(lo)), "r"(__float_as_uint(hi)));
    return r;
}
__device__ __forceinline__ float lo32(u64 v) { return __uint_as_float((u32)v); }
__device__ __forceinline__ float hi32(u64 v) { return __uint_as_float((u32)(v >> 32)); }
__device__ __forceinline__ u32 prmt_hi16(u32 a, u32 b) {
    u32 d;
    asm("prmt.b32 %0, %1, %2, 0x7632;" : "=r"(d) : "r"(a), "r"(b));
    return d;
}
__device__ __forceinline__ u32 cvt_bf16x2(float lo_v, float hi_v) {
    u32 d;
    asm("cvt.rn.bf16x2.f32 %0, %1, %2;" : "=r"(d) : "f"(hi_v), "f"(lo_v));
    return d;
}
__device__ __forceinline__ float hif(float h) {
    return __uint_as_float(__float_as_uint(h) & 0xffff0000u);
}

// ---- mma.sync m16n8k16 bf16 ----
__device__ __forceinline__ void mma_bias(float* d, const u32* a, uint2 b,
                                         float c0, float c1) {
    asm volatile("mma.sync.aligned.m16n8k16.row.col.f32.bf16.bf16.f32 "
        "{%0,%1,%2,%3}, {%4,%5,%6,%7}, {%8,%9}, {%10,%11,%10,%11};"
        : "=f"(d[0]), "=f"(d[1]), "=f"(d[2]), "=f"(d[3])
        : "r"(a[0]), "r"(a[1]), "r"(a[2]), "r"(a[3]),
          "r"(b.x), "r"(b.y), "f"(c0), "f"(c1));
}
__device__ __forceinline__ void mma_acc(float* d, const u32* a, uint2 b) {
    asm volatile("mma.sync.aligned.m16n8k16.row.col.f32.bf16.bf16.f32 "
        "{%0,%1,%2,%3}, {%4,%5,%6,%7}, {%8,%9}, {%0,%1,%2,%3};"
        : "+f"(d[0]), "+f"(d[1]), "+f"(d[2]), "+f"(d[3])
        : "r"(a[0]), "r"(a[1]), "r"(a[2]), "r"(a[3]),
          "r"(b.x), "r"(b.y));
}

__global__ void igann_init_kernel(float* __restrict__ out,
                                  const float* __restrict__ bias_b) {
    int i = blockIdx.x * blockDim.x + threadIdx.x;
    if (i < BATCH) out[i] = bias_b[0];
}

__global__ __launch_bounds__(TPB, 4) void igann_mma_kernel(
    const float* __restrict__ x,   // [B, F]
    const float* __restrict__ la,  // [F]
    const float* __restrict__ W1,  // [F, H]
    const float* __restrict__ b1,  // [F, H]
    const float* __restrict__ W2,  // [F, H(out j), H(in i)]
    const float* __restrict__ b2,  // [F, H]
    const float* __restrict__ W3,  // [F, H]
    const float* __restrict__ b3,  // [F]
    float* __restrict__ out)       // [B]
{
    __shared__ float sX[ROWS_CTA * XSTRIDE];   // 20 KB x tile (padded)
    __shared__ uint2 sBfrag[GF * 128];         // 16 KB B fragments
    __shared__ float4 sW1B1[GF * 8];           // (w1_i,b1_i,w1_{i+1},b1_{i+1})
    __shared__ u64 sB2p[GF * 8];
    __shared__ u64 sW3p[GF * 8];
    __shared__ float sA[GF];
    __shared__ float sB3sum;

    const int tid  = threadIdx.x;
    const int lane = tid & 31;
    const int wid  = tid >> 5;
    const int f0   = blockIdx.y * GF;
    const int rowCta = blockIdx.x * ROWS_CTA;

    // ---- stage x tile: 256 rows x 16 floats, line-efficient LDG ----
    #pragma unroll
    for (int t = 0; t < 8; t++) {
        int e  = tid + t * TPB;        // 0..1023 over (row, col4)
        int r  = e >> 2;
        int c4 = e & 3;
        float4 v = *(const float4*)(x + (size_t)(rowCta + r) * F_TOTAL
                                      + f0 + 4 * c4);
        *(float4*)(sX + r * XSTRIDE + 4 * c4) = v;
    }
    // ---- stage B fragments: W2 split hi(trunc) / lo(residual bf16) ----
    #pragma unroll
    for (int t = 0; t < 16; t++) {
        int e    = tid + t * TPB;      // 0..2047
        int fi   = e >> 7;
        int kt   = (e >> 6) & 1;
        int ns   = (e >> 5) & 1;
        int ln   = e & 31;
        int n    = ns * 8 + (ln >> 2);
        int kb   = (ln & 3) * 2;
        const float* wrow = W2 + (size_t)(f0 + fi) * 256 + n * H;
        u32 pk[2];
        #pragma unroll
        for (int hh = 0; hh < 2; hh++) {
            float w0 = wrow[kb + 8 * hh];
            float w1 = wrow[kb + 8 * hh + 1];
            u32 s0, s1;
            if (kt == 0) {
                s0 = __float_as_uint(w0) >> 16;
                s1 = __float_as_uint(w1) >> 16;
            } else {
                s0 = (u32)__bfloat16_as_ushort(__float2bfloat16(w0 - hif(w0)));
                s1 = (u32)__bfloat16_as_ushort(__float2bfloat16(w1 - hif(w1)));
            }
            pk[hh] = s0 | (s1 << 16);
        }
        sBfrag[e] = make_uint2(pk[0], pk[1]);
    }
    // ---- stage W1/b1, b2/W3 pairs ----
    {
        int fi = tid >> 3, p = tid & 7, i = 2 * p;
        float4 v;
        v.x = W1[(f0 + fi) * H + i];     v.y = b1[(f0 + fi) * H + i];
        v.z = W1[(f0 + fi) * H + i + 1]; v.w = b1[(f0 + fi) * H + i + 1];
        sW1B1[fi * 8 + p] = v;
        sB2p[fi * 8 + p] = pack2(b2[(f0 + fi) * H + i], b2[(f0 + fi) * H + i + 1]);
        sW3p[fi * 8 + p] = pack2(W3[(f0 + fi) * H + i], W3[(f0 + fi) * H + i + 1]);
    }
    if (tid < GF) sA[tid] = la[f0 + tid];
    if (tid == 0) {
        float s = 0.f;
        #pragma unroll
        for (int f = 0; f < GF; f++) s += b3[f0 + f];
        sB3sum = s;
    }
    __syncthreads();

    const int qrow = lane >> 2;                 // fragment row within 8-group
    const bool reducer = (lane & 3) == 0;
    // warp w, block b: rows rowCta + w*64 + b*32 + 8*rg + qrow
    const int wbase = wid * 64 + qrow;

    float acc[MT][4] = {{0.f, 0.f, 0.f, 0.f}, {0.f, 0.f, 0.f, 0.f}};
    float lin[MT][4] = {{0.f, 0.f, 0.f, 0.f}, {0.f, 0.f, 0.f, 0.f}};

    #pragma unroll 1
    for (int fi = 0; fi < GF; fi++) {
        // per-feature weights, held across both row-blocks
        const float4 wbA = sW1B1[fi * 8 + (lane & 3)];
        const float4 wbB = sW1B1[fi * 8 + (lane & 3) + 4];
        const uint2 bh0 = sBfrag[fi * 128 + lane];
        const uint2 bh1 = sBfrag[fi * 128 + 32 + lane];
        const uint2 bl0 = sBfrag[fi * 128 + 64 + lane];
        const uint2 bl1 = sBfrag[fi * 128 + 96 + lane];
        const u64 b2a = sB2p[fi * 8 + (lane & 3)];
        const u64 b2b = sB2p[fi * 8 + (lane & 3) + 4];
        const u64 w3a = sW3p[fi * 8 + (lane & 3)];
        const u64 w3b = sW3p[fi * 8 + (lane & 3) + 4];
        const float w30 = lo32(w3a), w31 = hi32(w3a);
        const float w38 = lo32(w3b), w39 = hi32(w3b);
        const float aF = sA[fi];

        #pragma unroll
        for (int b = 0; b < MT; b++) {
            // x for the 4 fragment row-groups (quad-broadcast LDS)
            float xf[4];
            #pragma unroll
            for (int rg = 0; rg < 4; rg++)
                xf[rg] = sX[(wbase + b * 32 + 8 * rg) * XSTRIDE + fi];

            if (reducer) {
                #pragma unroll
                for (int rg = 0; rg < 4; rg++)
                    lin[b][rg] = fmaf(aF, xf[rg], lin[b][rg]);
            }

            // A fragments: h1 computed directly into fragment slots
            u32 ahi[2][4], alo[2][4];
            #pragma unroll
            for (int rg = 0; rg < 4; rg++) {
                float xv = xf[rg];
                float h0 = fmaxf(fmaf(xv, wbA.x, wbA.y), 0.f);
                float h1 = fmaxf(fmaf(xv, wbA.z, wbA.w), 0.f);
                float h2 = fmaxf(fmaf(xv, wbB.x, wbB.y), 0.f);
                float h3 = fmaxf(fmaf(xv, wbB.z, wbB.w), 0.f);
                int mt = rg >> 1, sl = rg & 1;
                ahi[mt][sl]     = prmt_hi16(__float_as_uint(h0), __float_as_uint(h1));
                ahi[mt][2 + sl] = prmt_hi16(__float_as_uint(h2), __float_as_uint(h3));
                alo[mt][sl]     = cvt_bf16x2(h0 - hif(h0), h1 - hif(h1));
                alo[mt][2 + sl] = cvt_bf16x2(h2 - hif(h2), h3 - hif(h3));
            }

            // D = b2 + hi*Whi + lo*Whi + hi*Wlo
            float d[2][2][4];
            #pragma unroll
            for (int mt = 0; mt < 2; mt++) {
                mma_bias(d[mt][0], ahi[mt], bh0, lo32(b2a), hi32(b2a));
                mma_acc (d[mt][0], alo[mt], bh0);
                mma_acc (d[mt][0], ahi[mt], bl0);
                mma_bias(d[mt][1], ahi[mt], bh1, lo32(b2b), hi32(b2b));
                mma_acc (d[mt][1], alo[mt], bh1);
                mma_acc (d[mt][1], ahi[mt], bl1);
            }

            // scalar epilogue: acc += relu(D) . W3
            #pragma unroll
            for (int mt = 0; mt < 2; mt++) {
                #pragma unroll
                for (int hh = 0; hh < 2; hh++) {
                    int rg = 2 * mt + hh;
                    float t = acc[b][rg];
                    t = fmaf(fmaxf(d[mt][0][2 * hh],     0.f), w30, t);
                    t = fmaf(fmaxf(d[mt][0][2 * hh + 1], 0.f), w31, t);
                    t = fmaf(fmaxf(d[mt][1][2 * hh],     0.f), w38, t);
                    t = fmaf(fmaxf(d[mt][1][2 * hh + 1], 0.f), w39, t);
                    acc[b][rg] = t;
                }
            }
        }
    }

    // ---- reduce: quad butterfly; one atomic per row ----
    const float base = sB3sum;
    #pragma unroll
    for (int b = 0; b < MT; b++) {
        #pragma unroll
        for (int rg = 0; rg < 4; rg++) {
            float s = acc[b][rg];
            s += __shfl_xor_sync(0xffffffffu, s, 1);
            s += __shfl_xor_sync(0xffffffffu, s, 2);
            if (reducer) {
                int r = rowCta + wbase + b * 32 + 8 * rg;
                atomicAdd(&out[r], s + lin[b][rg] + base);
            }
        }
    }
}

extern "C" void kernel_launch(void* const* d_in, const int* in_sizes, int n_in,
                              void* d_out, int out_size) {
    const float* x      = (const float*)d_in[0];
    const float* la     = (const float*)d_in[1];
    const float* bias_b = (const float*)d_in[2];
    const float* W1     = (const float*)d_in[3];
    const float* b1     = (const float*)d_in[4];
    const float* W2     = (const float*)d_in[5];
    const float* b2     = (const float*)d_in[6];
    const float* W3     = (const float*)d_in[7];
    const float* b3     = (const float*)d_in[8];
    float* out = (float*)d_out;

    igann_init_kernel<<<BATCH / 256, 256>>>(out, bias_b);

    dim3 grid(BATCH / ROWS_CTA, NGROUPS);
    igann_mma_kernel<<<grid, TPB>>>(x, la, W1, b1, W2, b2, W3, b3, out);
}